// round 6
// baseline (speedup 1.0000x reference)
#include <cuda_runtime.h>
#include <cuda_bf16.h>
#include <cuda_fp16.h>
#include <cstdint>

// ---------------- problem constants ----------------
#define T_TOKENS 32768
#define E_DIM    512
#define GROUPS   4
#define DIM      128      // per-group dim (K)
#define KCODES   512      // codes per group (N)

#define MT       128      // tokens per CTA
#define NT       64       // codes per N-tile
#define NTILES   (KCODES / NT)   // 8
#define THREADS  256

#define MARGIN   1e-3f    // >= 2*(mma 3-pass err + fp16 store err + ulp(128) slop)

// SMEM layout (bytes). A/B rows = 128 bf16 = 256B, 16B-chunk swizzle c^(r&7).
#define A0_OFF   0            // 128*256 = 32768
#define A1_OFF   32768
#define B0_OFF   65536        // 64*256 = 16384
#define B1_OFF   81920
#define S_OFF    98304        // 128 rows * 257 u32 (half2) = 131584
#define S_STRIDE 257          // u32 stride per token row (514 fp16 cols, 512 used)
#define BK_OFF   229888       // 128*4
#define PK_OFF   230400       // 128*8
#define SMIN_OFF 231424       // 128*4
#define RED_OFF  231936       // 8*8
#define SMEM_TOTAL 232000

__device__ __nv_bfloat16 g_wb0[GROUPS * KCODES * DIM];
__device__ __nv_bfloat16 g_wb1[GROUPS * KCODES * DIM];
__device__ float         g_wsq[GROUPS * KCODES];
__device__ double        g_loss_acc;

__global__ void vq_init_kernel() { g_loss_acc = 0.0; }

__global__ void vq_finalize_kernel(float* out, long long loss_index) {
    out[loss_index] = (float)(g_loss_acc * (1.25 / 4194304.0));
}

// Split W into two bf16 levels + exact wsq (sequential fp32 chain, ref order).
__global__ void vq_prep_kernel(const float* __restrict__ w0, const float* __restrict__ w1,
                               const float* __restrict__ w2, const float* __restrict__ w3)
{
    int r = blockIdx.x * blockDim.x + threadIdx.x;
    if (r >= GROUPS * KCODES) return;
    int g = r >> 9, k = r & (KCODES - 1);
    const float* W = (g == 0) ? w0 : (g == 1) ? w1 : (g == 2) ? w2 : w3;
    const float* row = W + (size_t)k * DIM;
    float s = 0.0f;
    #pragma unroll 4
    for (int d = 0; d < DIM; ++d) {
        float x = row[d];
        s = fmaf(x, x, s);
        __nv_bfloat16 b0 = __float2bfloat16_rn(x);
        float r1 = x - __bfloat162float(b0);
        __nv_bfloat16 b1 = __float2bfloat16_rn(r1);
        g_wb0[(size_t)r * DIM + d] = b0;
        g_wb1[(size_t)r * DIM + d] = b1;
    }
    g_wsq[r] = s;
}

__device__ __forceinline__ uint32_t smem_u32p(const void* p) {
    uint32_t a;
    asm("{ .reg .u64 t; cvta.to.shared.u64 t, %1; cvt.u32.u64 %0, t; }" : "=r"(a) : "l"(p));
    return a;
}
__device__ __forceinline__ void ldsm_x4(uint32_t& r0, uint32_t& r1, uint32_t& r2, uint32_t& r3,
                                        uint32_t addr) {
    asm volatile("ldmatrix.sync.aligned.m8n8.x4.shared.b16 {%0,%1,%2,%3}, [%4];"
                 : "=r"(r0), "=r"(r1), "=r"(r2), "=r"(r3) : "r"(addr));
}
__device__ __forceinline__ void mma_bf16(float* c, const uint32_t* a, uint32_t b0, uint32_t b1) {
    asm volatile("mma.sync.aligned.m16n8k16.row.col.f32.bf16.bf16.f32 "
                 "{%0,%1,%2,%3}, {%4,%5,%6,%7}, {%8,%9}, {%0,%1,%2,%3};"
                 : "+f"(c[0]), "+f"(c[1]), "+f"(c[2]), "+f"(c[3])
                 : "r"(a[0]), "r"(a[1]), "r"(a[2]), "r"(a[3]), "r"(b0), "r"(b1));
}

__global__ __launch_bounds__(THREADS, 1)
void vq_main_kernel(const float* __restrict__ latents,
                    const float* __restrict__ w0, const float* __restrict__ w1,
                    const float* __restrict__ w2, const float* __restrict__ w3,
                    float* __restrict__ out)
{
    extern __shared__ char sm[];
    const uint32_t sb = smem_u32p(sm);

    uint32_t*  s_u32   = (uint32_t*)(sm + S_OFF);
    int*       bk_sm   = (int*)(sm + BK_OFF);
    uint64_t*  pk_sm   = (uint64_t*)(sm + PK_OFF);
    float*     smin_sm = (float*)(sm + SMIN_OFF);
    double*    red     = (double*)(sm + RED_OFF);

    const int g  = blockIdx.y;
    const int t0 = blockIdx.x * MT;
    const float* __restrict__ W = (g == 0) ? w0 : (g == 1) ? w1 : (g == 2) ? w2 : w3;
    const float* __restrict__ wsqg = g_wsq + g * KCODES;

    const int tid  = threadIdx.x;
    const int wid  = tid >> 5;
    const int lane = tid & 31;
    const int wm   = wid >> 1;   // warp m index (0..3) -> rows wm*32..+31
    const int wn   = wid & 1;    // warp n index (0..1) -> cols wn*32..+31 within N-tile
    const int gid  = lane >> 2;
    const int qid  = lane & 3;

    // ---- load X tile, split to bf16 A0/A1 in smem (swizzled 16B chunks) ----
    #pragma unroll
    for (int it = 0; it < 16; ++it) {
        int idx = tid + it * THREADS;          // 0..4095 float4s
        int m   = idx >> 5;
        int c4  = idx & 31;
        float4 v = *(const float4*)(latents + (size_t)(t0 + m) * E_DIM + g * DIM + c4 * 4);
        float xv[4] = {v.x, v.y, v.z, v.w};
        uint16_t p0[4], p1[4];
        #pragma unroll
        for (int q = 0; q < 4; ++q) {
            __nv_bfloat16 b0 = __float2bfloat16_rn(xv[q]);
            float r1 = xv[q] - __bfloat162float(b0);
            __nv_bfloat16 b1 = __float2bfloat16_rn(r1);
            p0[q] = *(uint16_t*)&b0; p1[q] = *(uint16_t*)&b1;
        }
        uint64_t q0 = (uint64_t)p0[0] | ((uint64_t)p0[1] << 16) | ((uint64_t)p0[2] << 32) | ((uint64_t)p0[3] << 48);
        uint64_t q1 = (uint64_t)p1[0] | ((uint64_t)p1[1] << 16) | ((uint64_t)p1[2] << 32) | ((uint64_t)p1[3] << 48);
        int chunk = c4 >> 1, half = c4 & 1;
        uint32_t off = (uint32_t)m * 256u + (uint32_t)((chunk ^ (m & 7)) << 4) + (uint32_t)(half << 3);
        *(uint64_t*)(sm + A0_OFF + off) = q0;
        *(uint64_t*)(sm + A1_OFF + off) = q1;
    }

    // ---- N-tile loop ----
    for (int ct = 0; ct < NTILES; ++ct) {
        __syncthreads();   // prior tile's MMA readers done before overwriting B
        // load B tile (64 codes x 128 dims, both levels), swizzled
        {
            const __nv_bfloat16* src0 = g_wb0 + ((size_t)(g * KCODES + ct * NT)) * DIM;
            const __nv_bfloat16* src1 = g_wb1 + ((size_t)(g * KCODES + ct * NT)) * DIM;
            #pragma unroll
            for (int it = 0; it < 4; ++it) {
                int idx = tid + it * THREADS;    // 0..1023 uint4s
                int r   = idx >> 4;
                int c   = idx & 15;
                uint4 v0 = *(const uint4*)(src0 + (size_t)r * DIM + c * 8);
                uint4 v1 = *(const uint4*)(src1 + (size_t)r * DIM + c * 8);
                uint32_t off = (uint32_t)r * 256u + (uint32_t)((c ^ (r & 7)) << 4);
                *(uint4*)(sm + B0_OFF + off) = v0;
                *(uint4*)(sm + B1_OFF + off) = v1;
            }
        }
        __syncthreads();

        float acc[2][4][4];
        #pragma unroll
        for (int i = 0; i < 2; ++i)
            #pragma unroll
            for (int j = 0; j < 4; ++j)
                #pragma unroll
                for (int q = 0; q < 4; ++q) acc[i][j][q] = 0.0f;

        #pragma unroll
        for (int pass = 0; pass < 3; ++pass) {
            const uint32_t Ab = sb + ((pass == 2) ? A1_OFF : A0_OFF);
            const uint32_t Bb = sb + ((pass == 1) ? B1_OFF : B0_OFF);
            #pragma unroll
            for (int ks = 0; ks < 8; ++ks) {
                int chunk = ks * 2 + (lane >> 4);
                uint32_t a[2][4], b[2][4];
                #pragma unroll
                for (int i = 0; i < 2; ++i) {
                    int row = wm * 32 + i * 16 + (lane & 15);
                    uint32_t addr = Ab + (uint32_t)row * 256u + (uint32_t)((chunk ^ (row & 7)) << 4);
                    ldsm_x4(a[i][0], a[i][1], a[i][2], a[i][3], addr);
                }
                #pragma unroll
                for (int jj = 0; jj < 2; ++jj) {
                    int row = wn * 32 + jj * 16 + (lane & 15);
                    uint32_t addr = Bb + (uint32_t)row * 256u + (uint32_t)((chunk ^ (row & 7)) << 4);
                    ldsm_x4(b[jj][0], b[jj][1], b[jj][2], b[jj][3], addr);
                }
                #pragma unroll
                for (int i = 0; i < 2; ++i)
                    #pragma unroll
                    for (int j = 0; j < 4; ++j)
                        mma_bf16(acc[i][j], a[i], b[j >> 1][j & 1], b[j >> 1][2 + (j & 1)]);
            }
        }

        // s = wsq - 2*cross  -> fp16 pairs in smem
        #pragma unroll
        for (int i = 0; i < 2; ++i) {
            int row0 = wm * 32 + i * 16 + gid;
            #pragma unroll
            for (int j = 0; j < 4; ++j) {
                int colp = ct * 32 + wn * 16 + j * 4 + qid;   // u32 (code-pair) index
                int c0 = colp * 2;
                float ws0 = __ldg(wsqg + c0), ws1 = __ldg(wsqg + c0 + 1);
                float s00 = fmaf(-2.0f, acc[i][j][0], ws0);
                float s01 = fmaf(-2.0f, acc[i][j][1], ws1);
                float s10 = fmaf(-2.0f, acc[i][j][2], ws0);
                float s11 = fmaf(-2.0f, acc[i][j][3], ws1);
                __half2 h0 = __floats2half2_rn(s00, s01);
                __half2 h1 = __floats2half2_rn(s10, s11);
                s_u32[row0 * S_STRIDE + colp]       = *(uint32_t*)&h0;
                s_u32[(row0 + 8) * S_STRIDE + colp] = *(uint32_t*)&h1;
            }
        }
    }
    __syncthreads();

    // ---- scan: token t handled by threads (t, t+128) over halves of 512 codes ----
    const int t = tid & 127;
    const int h = tid >> 7;
    const uint32_t* srow = s_u32 + t * S_STRIDE + h * 128;

    float smin = 3.402823466e38f;
    #pragma unroll 8
    for (int i = 0; i < 128; ++i) {
        __half2 hv = *(const __half2*)(srow + i);
        float2 f = __half22float2(hv);
        smin = fminf(smin, fminf(f.x, f.y));
    }
    if (h == 1) smin_sm[t] = smin;
    __syncthreads();
    if (h == 0) smin_sm[t] = fminf(smin, smin_sm[t]);
    __syncthreads();
    const float thr = smin_sm[t] + MARGIN;

    // exact xsq (sequential chain, ref order)
    const float* xrow = latents + (size_t)(t0 + t) * E_DIM + g * DIM;
    float xsq = 0.0f;
    #pragma unroll 4
    for (int d = 0; d < DIM; ++d) xsq = fmaf(xrow[d], xrow[d], xsq);

    // candidate refinement: exact ref-formula distance, packed (dd,k) lexicographic min
    uint64_t best = ~0ull;
    for (int i = 0; i < 128; ++i) {
        __half2 hv = *(const __half2*)(srow + i);
        float2 f = __half22float2(hv);
        #pragma unroll
        for (int sub = 0; sub < 2; ++sub) {
            float sv = (sub == 0) ? f.x : f.y;
            if (sv <= thr) {
                int k = h * 256 + i * 2 + sub;
                const float* wr = W + (size_t)k * DIM;
                float cr = 0.0f;
                #pragma unroll 4
                for (int d = 0; d < DIM; ++d) cr = fmaf(xrow[d], wr[d], cr);
                float tt = xsq + __ldg(wsqg + k);     // fl(x_sq + w_sq)
                float dd = fmaf(-2.0f, cr, tt);       // fl(t - 2*cross): exact ref formula
                uint64_t pk = ((uint64_t)__float_as_uint(dd) << 32) | (uint32_t)k;
                best = (pk < best) ? pk : best;
            }
        }
    }
    if (h == 1) pk_sm[t] = best;
    __syncthreads();
    if (h == 0) {
        uint64_t o = pk_sm[t];
        if (o < best) best = o;
        bk_sm[t] = (int)(best & 0xffffffffu);
    }
    __syncthreads();

    // ---- output + loss ----
    double lsum = 0.0;
    #pragma unroll
    for (int it = 0; it < 16; ++it) {
        int idx = tid + it * THREADS;
        int mm  = idx >> 5;
        int c4  = idx & 31;
        int k   = bk_sm[mm];
        float4 q = *(const float4*)(W + (size_t)k * DIM + c4 * 4);
        float4 x = *(const float4*)(latents + (size_t)(t0 + mm) * E_DIM + g * DIM + c4 * 4);
        float dx = q.x - x.x, dy = q.y - x.y, dz = q.z - x.z, dw = q.w - x.w;
        float4 o;
        o.x = x.x + dx; o.y = x.y + dy; o.z = x.z + dz; o.w = x.w + dw;   // x + (q - x), as ref
        *(float4*)(out + (size_t)(t0 + mm) * E_DIM + g * DIM + c4 * 4) = o;
        lsum += (double)dx * dx + (double)dy * dy + (double)dz * dz + (double)dw * dw;
    }
    #pragma unroll
    for (int off = 16; off; off >>= 1)
        lsum += __shfl_xor_sync(0xffffffffu, lsum, off);
    if (lane == 0) red[wid] = lsum;
    __syncthreads();
    if (tid == 0) {
        double s = 0.0;
        #pragma unroll
        for (int w = 0; w < 8; ++w) s += red[w];
        atomicAdd(&g_loss_acc, s);
    }
}

extern "C" void kernel_launch(void* const* d_in, const int* in_sizes, int n_in,
                              void* d_out, int out_size) {
    const float* latents = (const float*)d_in[0];
    const float* w1 = (const float*)d_in[1];
    const float* w2 = (const float*)d_in[2];
    const float* w3 = (const float*)d_in[3];
    const float* w4 = (const float*)d_in[4];
    float* out = (float*)d_out;

    cudaFuncSetAttribute(vq_main_kernel, cudaFuncAttributeMaxDynamicSharedMemorySize, SMEM_TOTAL);

    vq_init_kernel<<<1, 1>>>();
    vq_prep_kernel<<<(GROUPS * KCODES + 255) / 256, 256>>>(w1, w2, w3, w4);
    dim3 grid(T_TOKENS / MT, GROUPS);
    vq_main_kernel<<<grid, THREADS, SMEM_TOTAL>>>(latents, w1, w2, w3, w4, out);
    vq_finalize_kernel<<<1, 1>>>(out, (long long)out_size - 1);
}